// round 2
// baseline (speedup 1.0000x reference)
#include <cuda_runtime.h>
#include <cuda_bf16.h>

// ---------------------------------------------------------------------------
// GCN_40037685134216: 4-layer GCN + mean-pool + MLP head, fp32.
// N=100000 nodes, E=1600000 edges, D=128, 512 graphs.
// NOTE: edge_index / batch are int32 (jax x64 disabled downcasts int64).
// ---------------------------------------------------------------------------

#define MAX_N 100000
#define MAX_E 1600000
#define DD    128
#define MAX_G 512

// Static scratch (allocation-free rule).
__device__ __align__(16) float  g_deg [MAX_N];            // degree -> dinv (in place)
__device__ __align__(16) float  g_norm[MAX_E];
__device__ float4 g_xw [MAX_N * (DD/4)];                  // h @ W
__device__ float4 g_hA [MAX_N * (DD/4)];
__device__ float4 g_hB [MAX_N * (DD/4)];
__device__ float4 g_psum[MAX_G * (DD/4)];
__device__ float  g_pcnt[MAX_G];

// ---------------------------------------------------------------------------
// Degree / normalization precompute
// ---------------------------------------------------------------------------
__global__ void k_init_deg(float* deg, int N) {
    int i = blockIdx.x * blockDim.x + threadIdx.x;
    if (i < N) deg[i] = 1.0f;   // self loop
}

__global__ void k_deg_accum(const int* __restrict__ ei, float* deg, int E) {
    int e = blockIdx.x * blockDim.x + threadIdx.x;
    if (e < E) {
        int c = ei[E + e];               // edge_index[1] = target
        atomicAdd(&deg[c], 1.0f);
    }
}

__global__ void k_finalize_dinv(float* deg, int N) {
    int i = blockIdx.x * blockDim.x + threadIdx.x;
    if (i < N) deg[i] = rsqrtf(deg[i]);  // deg >= 1 always
}

__global__ void k_prep_edges(const int* __restrict__ ei,
                             const float* __restrict__ dinv,
                             float* __restrict__ nrm, int E) {
    int e = blockIdx.x * blockDim.x + threadIdx.x;
    if (e < E) {
        int r = ei[e];
        int c = ei[E + e];
        nrm[e] = dinv[r] * dinv[c];
    }
}

// ---------------------------------------------------------------------------
// SGEMM: C[M,128] = act(A[M,128]) @ W[128,128]; act = relu if applyRelu
// BM=BN=128, BK=16, 256 threads, 8x8 register tile.
// ---------------------------------------------------------------------------
#define BM 128
#define BN 128
#define BK 16
#define TM 8
#define TN 8

__global__ __launch_bounds__(256)
void k_gemm(const float4* __restrict__ A4, const float4* __restrict__ W4,
            float4* __restrict__ C4, int M, int applyRelu) {
    __shared__ float As[BK][BM];
    __shared__ float Bs[BK][BN];

    const int tid = threadIdx.x;
    const int tx  = tid & 15;
    const int ty  = tid >> 4;
    const int m0  = blockIdx.x * BM;

    float acc[TM][TN];
#pragma unroll
    for (int i = 0; i < TM; i++)
#pragma unroll
        for (int j = 0; j < TN; j++) acc[i][j] = 0.0f;

#pragma unroll
    for (int k0 = 0; k0 < DD; k0 += BK) {
        // Load A tile (128 rows x 16 k), transpose into As[k][m]
#pragma unroll
        for (int i = 0; i < 2; i++) {
            int id = tid + i * 256;          // 0..511
            int m  = id >> 2;                // 0..127
            int kq = id & 3;                 // float4 index within 16-k chunk
            float4 v = make_float4(0.f, 0.f, 0.f, 0.f);
            int gr = m0 + m;
            if (gr < M) v = A4[gr * (DD/4) + (k0 >> 2) + kq];
            if (applyRelu) {
                v.x = fmaxf(v.x, 0.f); v.y = fmaxf(v.y, 0.f);
                v.z = fmaxf(v.z, 0.f); v.w = fmaxf(v.w, 0.f);
            }
            int kb = kq * 4;
            As[kb + 0][m] = v.x; As[kb + 1][m] = v.y;
            As[kb + 2][m] = v.z; As[kb + 3][m] = v.w;
        }
        // Load B tile (16 k x 128 n), direct copy
#pragma unroll
        for (int i = 0; i < 2; i++) {
            int id = tid + i * 256;          // 0..511
            int kk = id >> 5;                // 0..15
            int nq = id & 31;                // 0..31 float4 cols
            float4 v = W4[(k0 + kk) * (DD/4) + nq];
            *(float4*)&Bs[kk][nq * 4] = v;
        }
        __syncthreads();

#pragma unroll
        for (int kk = 0; kk < BK; kk++) {
            float a[TM], b[TN];
            *(float4*)&a[0] = *(const float4*)&As[kk][ty * TM];
            *(float4*)&a[4] = *(const float4*)&As[kk][ty * TM + 4];
            *(float4*)&b[0] = *(const float4*)&Bs[kk][tx * TN];
            *(float4*)&b[4] = *(const float4*)&Bs[kk][tx * TN + 4];
#pragma unroll
            for (int i = 0; i < TM; i++)
#pragma unroll
                for (int j = 0; j < TN; j++)
                    acc[i][j] += a[i] * b[j];
        }
        __syncthreads();
    }

#pragma unroll
    for (int i = 0; i < TM; i++) {
        int gr = m0 + ty * TM + i;
        if (gr < M) {
            float4 v0 = make_float4(acc[i][0], acc[i][1], acc[i][2], acc[i][3]);
            float4 v1 = make_float4(acc[i][4], acc[i][5], acc[i][6], acc[i][7]);
            C4[gr * (DD/4) + (tx * TN) / 4]     = v0;
            C4[gr * (DD/4) + (tx * TN) / 4 + 1] = v1;
        }
    }
}

// ---------------------------------------------------------------------------
// out[i] = bias + xw[i] * dinv[i]^2   (self-loop contribution + bias)
// one thread per float4
// ---------------------------------------------------------------------------
__global__ void k_init_out(float4* __restrict__ out4, const float4* __restrict__ xw4,
                           const float* __restrict__ dinv, const float* __restrict__ bias,
                           int N) {
    int t = blockIdx.x * blockDim.x + threadIdx.x;
    if (t >= N * (DD/4)) return;
    int node = t >> 5;            // /32
    int q    = t & 31;
    float di = dinv[node];
    float s  = di * di;
    float4 v = xw4[t];
    const float4 b = *(const float4*)&bias[q * 4];
    v.x = v.x * s + b.x; v.y = v.y * s + b.y;
    v.z = v.z * s + b.z; v.w = v.w * s + b.w;
    out4[t] = v;
}

// ---------------------------------------------------------------------------
// Scatter: out[col] += xw[row] * norm.  One warp per edge, vector f32 red.
// ---------------------------------------------------------------------------
__device__ __forceinline__ void red_add_v4(float* addr, float4 v) {
    asm volatile("red.global.add.v4.f32 [%0], {%1, %2, %3, %4};"
                 :: "l"(addr), "f"(v.x), "f"(v.y), "f"(v.z), "f"(v.w)
                 : "memory");
}

__global__ __launch_bounds__(256)
void k_scatter(const float4* __restrict__ xw4,
               const int* __restrict__ ei,
               const float* __restrict__ nrm,
               float4* __restrict__ out4, int E) {
    int warp = (blockIdx.x * blockDim.x + threadIdx.x) >> 5;
    int lane = threadIdx.x & 31;
    if (warp >= E) return;
    int   r  = ei[warp];          // source
    int   c  = ei[E + warp];      // target
    float nm = nrm[warp];
    float4 v = xw4[r * (DD/4) + lane];
    v.x *= nm; v.y *= nm; v.z *= nm; v.w *= nm;
    red_add_v4((float*)(out4 + c * (DD/4) + lane), v);
}

// ---------------------------------------------------------------------------
// Pooling
// ---------------------------------------------------------------------------
__global__ void k_zero_pool(float4* psum, float* pcnt, int G) {
    int t = blockIdx.x * blockDim.x + threadIdx.x;
    if (t < G * (DD/4)) psum[t] = make_float4(0.f, 0.f, 0.f, 0.f);
    if (t < G) pcnt[t] = 0.f;
}

__global__ __launch_bounds__(256)
void k_pool(const float4* __restrict__ h4, const int* __restrict__ batch,
            float4* __restrict__ psum, float* __restrict__ pcnt, int N) {
    int warp = (blockIdx.x * blockDim.x + threadIdx.x) >> 5;
    int lane = threadIdx.x & 31;
    if (warp >= N) return;
    int g = batch[warp];
    float4 v = h4[warp * (DD/4) + lane];
    red_add_v4((float*)(psum + g * (DD/4) + lane), v);
    if (lane == 0) atomicAdd(&pcnt[g], 1.0f);
}

// ---------------------------------------------------------------------------
// MLP head: pooled(D) -> 100 -> 4.  One block per graph.
// ---------------------------------------------------------------------------
__global__ __launch_bounds__(128)
void k_mlp(const float4* __restrict__ psum, const float* __restrict__ pcnt,
           const float* __restrict__ w1, const float* __restrict__ b1,
           const float* __restrict__ w2, const float* __restrict__ b2,
           float* __restrict__ out, int H) {
    __shared__ float p[DD];
    __shared__ float hid[128];
    int g   = blockIdx.x;
    int tid = threadIdx.x;

    float cnt = fmaxf(pcnt[g], 1.0f);
    float inv = 1.0f / cnt;
    const float* ps = (const float*)(psum + g * (DD/4));
    p[tid] = ps[tid] * inv;
    __syncthreads();

    if (tid < H) {
        float s = b1[tid];
#pragma unroll 8
        for (int k = 0; k < DD; k++) s += p[k] * w1[k * H + tid];
        hid[tid] = fmaxf(s, 0.f);
    }
    __syncthreads();

    if (tid < 4) {
        float s = b2[tid];
        for (int j = 0; j < H; j++) s += hid[j] * w2[j * 4 + tid];
        out[g * 4 + tid] = s;
    }
}

// ---------------------------------------------------------------------------
// Launch
// ---------------------------------------------------------------------------
extern "C" void kernel_launch(void* const* d_in, const int* in_sizes, int n_in,
                              void* d_out, int out_size) {
    const float* x     = (const float*)d_in[0];
    const float* Ws    = (const float*)d_in[1];
    const float* bs    = (const float*)d_in[2];
    const float* w1    = (const float*)d_in[3];
    const float* b1    = (const float*)d_in[4];
    const float* w2    = (const float*)d_in[5];
    const float* b2    = (const float*)d_in[6];
    const int*   ei    = (const int*)d_in[7];
    const int*   batch = (const int*)d_in[8];
    float*       out   = (float*)d_out;

    const int N = in_sizes[8];          // 100000
    const int E = in_sizes[7] / 2;      // 1600000
    const int G = out_size / 4;         // 512
    const int H = in_sizes[4];          // 100

    float *deg, *nrm, *pcnt;
    float4 *xw, *hA, *hB, *psum;
    cudaGetSymbolAddress((void**)&deg,  g_deg);
    cudaGetSymbolAddress((void**)&nrm,  g_norm);
    cudaGetSymbolAddress((void**)&xw,   g_xw);
    cudaGetSymbolAddress((void**)&hA,   g_hA);
    cudaGetSymbolAddress((void**)&hB,   g_hB);
    cudaGetSymbolAddress((void**)&psum, g_psum);
    cudaGetSymbolAddress((void**)&pcnt, g_pcnt);

    const int T = 256;

    // normalization precompute
    k_init_deg     <<<(N + T - 1) / T, T>>>(deg, N);
    k_deg_accum    <<<(E + T - 1) / T, T>>>(ei, deg, E);
    k_finalize_dinv<<<(N + T - 1) / T, T>>>(deg, N);
    k_prep_edges   <<<(E + T - 1) / T, T>>>(ei, deg, nrm, E);

    // 4 GCN layers
    const float4* hin = (const float4*)x;
    const int gemmBlocks = (N + BM - 1) / BM;
    const int f4Blocks   = (N * (DD/4) + T - 1) / T;
    const int scatBlocks = (E + 7) / 8;     // 8 warps per block, 1 edge/warp
    for (int L = 0; L < 4; L++) {
        const float4* W4 = (const float4*)(Ws + (size_t)L * DD * DD);
        k_gemm<<<gemmBlocks, 256>>>(hin, W4, xw, N, L > 0 ? 1 : 0);
        float4* hout = (L & 1) ? hB : hA;
        k_init_out<<<f4Blocks, T>>>(hout, xw, deg, bs + L * DD, N);
        k_scatter <<<scatBlocks, 256>>>(xw, ei, nrm, hout, E);
        hin = hout;
    }

    // pooling + MLP
    k_zero_pool<<<(G * (DD/4) + T - 1) / T, T>>>(psum, pcnt, G);
    k_pool     <<<(N + 7) / 8, 256>>>(hin, batch, psum, pcnt, N);
    k_mlp      <<<G, 128>>>(psum, pcnt, w1, b1, w2, b2, out, H);
}

// round 3
// speedup vs baseline: 1.1149x; 1.1149x over previous
#include <cuda_runtime.h>
#include <cuda_bf16.h>

// ---------------------------------------------------------------------------
// GCN_40037685134216: 4-layer GCN + mean-pool + MLP head, fp32.
// N=100000 nodes, E=1600000 edges, D=128, 512 graphs.
// R3: CSR-by-target scatter (no atomics), y = dinv*(h@W) fused in GEMM epilogue.
//     out[c] = b + dinv[c]*( y[c] + sum_{in-edges} y[r] )
// ---------------------------------------------------------------------------

#define MAX_N 100000
#define MAX_E 1600000
#define DD    128
#define MAX_G 512

__device__ __align__(16) int    g_cnt [MAX_N];      // degree count / cursor
__device__ __align__(16) int    g_rowptr[MAX_N + 1];
__device__ __align__(16) int    g_cur [MAX_N];
__device__ __align__(16) int    g_eadj[MAX_E];
__device__ __align__(16) float  g_dinv[MAX_N];
__device__ float4 g_y  [MAX_N * (DD/4)];
__device__ float4 g_hA [MAX_N * (DD/4)];
__device__ float4 g_hB [MAX_N * (DD/4)];
__device__ float4 g_psum[MAX_G * (DD/4)];
__device__ float  g_pcnt[MAX_G];

// ---------------------------------------------------------------------------
// CSR build
// ---------------------------------------------------------------------------
__global__ void k_zero_cnt(int* cnt, int N) {
    int i = blockIdx.x * blockDim.x + threadIdx.x;
    if (i < N) cnt[i] = 0;
}

__global__ void k_count(const int* __restrict__ ei, int* cnt, int E) {
    int e = blockIdx.x * blockDim.x + threadIdx.x;
    if (e < E) atomicAdd(&cnt[ei[E + e]], 1);
}

__global__ void k_dinv(const int* __restrict__ cnt, float* dinv, int N) {
    int i = blockIdx.x * blockDim.x + threadIdx.x;
    if (i < N) dinv[i] = rsqrtf((float)cnt[i] + 1.0f);  // +1 self loop
}

// Single-block exclusive scan: rowptr[i] = sum cnt[0..i-1]; rowptr[N] = E.
__global__ __launch_bounds__(1024)
void k_scan(const int* __restrict__ cnt, int* __restrict__ rowptr, int N) {
    __shared__ int sums[1024];
    int t = threadIdx.x;
    int chunk = (N + 1023) / 1024;
    int beg = t * chunk;
    int end = min(beg + chunk, N);
    int s = 0;
    for (int i = beg; i < end; i++) s += cnt[i];
    sums[t] = s;
    __syncthreads();
    // Hillis-Steele inclusive scan
    for (int off = 1; off < 1024; off <<= 1) {
        int v = (t >= off) ? sums[t - off] : 0;
        __syncthreads();
        sums[t] += v;
        __syncthreads();
    }
    int run = (t > 0) ? sums[t - 1] : 0;
    for (int i = beg; i < end; i++) { rowptr[i] = run; run += cnt[i]; }
    if (end == N) rowptr[N] = run;
}

__global__ void k_copy_cur(const int* __restrict__ rowptr, int* cur, int N) {
    int i = blockIdx.x * blockDim.x + threadIdx.x;
    if (i < N) cur[i] = rowptr[i];
}

__global__ void k_fill(const int* __restrict__ ei, int* cur,
                       int* __restrict__ eadj, int E) {
    int e = blockIdx.x * blockDim.x + threadIdx.x;
    if (e < E) {
        int r = ei[e];
        int c = ei[E + e];
        int pos = atomicAdd(&cur[c], 1);
        eadj[pos] = r;
    }
}

// ---------------------------------------------------------------------------
// SGEMM: Y[M,128] = dinv[m] * ( act(A[M,128]) @ W[128,128] )
// BM=BN=128, BK=16, 256 threads, 8x8 register tile.
// ---------------------------------------------------------------------------
#define BM 128
#define BN 128
#define BK 16
#define TM 8
#define TN 8

__global__ __launch_bounds__(256)
void k_gemm(const float4* __restrict__ A4, const float4* __restrict__ W4,
            float4* __restrict__ Y4, const float* __restrict__ dinv,
            int M, int applyRelu) {
    __shared__ float As[BK][BM];
    __shared__ float Bs[BK][BN];

    const int tid = threadIdx.x;
    const int tx  = tid & 15;
    const int ty  = tid >> 4;
    const int m0  = blockIdx.x * BM;

    float acc[TM][TN];
#pragma unroll
    for (int i = 0; i < TM; i++)
#pragma unroll
        for (int j = 0; j < TN; j++) acc[i][j] = 0.0f;

#pragma unroll
    for (int k0 = 0; k0 < DD; k0 += BK) {
#pragma unroll
        for (int i = 0; i < 2; i++) {
            int id = tid + i * 256;          // 0..511
            int m  = id >> 2;                // 0..127
            int kq = id & 3;                 // float4 index within 16-k chunk
            float4 v = make_float4(0.f, 0.f, 0.f, 0.f);
            int gr = m0 + m;
            if (gr < M) v = A4[gr * (DD/4) + (k0 >> 2) + kq];
            if (applyRelu) {
                v.x = fmaxf(v.x, 0.f); v.y = fmaxf(v.y, 0.f);
                v.z = fmaxf(v.z, 0.f); v.w = fmaxf(v.w, 0.f);
            }
            int kb = kq * 4;
            As[kb + 0][m] = v.x; As[kb + 1][m] = v.y;
            As[kb + 2][m] = v.z; As[kb + 3][m] = v.w;
        }
#pragma unroll
        for (int i = 0; i < 2; i++) {
            int id = tid + i * 256;
            int kk = id >> 5;
            int nq = id & 31;
            float4 v = W4[(k0 + kk) * (DD/4) + nq];
            *(float4*)&Bs[kk][nq * 4] = v;
        }
        __syncthreads();

#pragma unroll
        for (int kk = 0; kk < BK; kk++) {
            float a[TM], b[TN];
            *(float4*)&a[0] = *(const float4*)&As[kk][ty * TM];
            *(float4*)&a[4] = *(const float4*)&As[kk][ty * TM + 4];
            *(float4*)&b[0] = *(const float4*)&Bs[kk][tx * TN];
            *(float4*)&b[4] = *(const float4*)&Bs[kk][tx * TN + 4];
#pragma unroll
            for (int i = 0; i < TM; i++)
#pragma unroll
                for (int j = 0; j < TN; j++)
                    acc[i][j] += a[i] * b[j];
        }
        __syncthreads();
    }

#pragma unroll
    for (int i = 0; i < TM; i++) {
        int gr = m0 + ty * TM + i;
        if (gr < M) {
            float di = dinv[gr];
            float4 v0 = make_float4(acc[i][0] * di, acc[i][1] * di,
                                    acc[i][2] * di, acc[i][3] * di);
            float4 v1 = make_float4(acc[i][4] * di, acc[i][5] * di,
                                    acc[i][6] * di, acc[i][7] * di);
            Y4[gr * (DD/4) + (tx * TN) / 4]     = v0;
            Y4[gr * (DD/4) + (tx * TN) / 4 + 1] = v1;
        }
    }
}

// ---------------------------------------------------------------------------
// CSR scatter: one warp per node.
// out[c] = bias + dinv[c] * ( y[c] + sum_{e in-edges} y[src(e)] )
// ---------------------------------------------------------------------------
__global__ __launch_bounds__(256)
void k_scatter_csr(const float4* __restrict__ y4,
                   const int* __restrict__ rowptr,
                   const int* __restrict__ eadj,
                   const float* __restrict__ dinv,
                   const float* __restrict__ bias,
                   float4* __restrict__ out4, int N) {
    int node = (blockIdx.x * blockDim.x + threadIdx.x) >> 5;
    int lane = threadIdx.x & 31;
    if (node >= N) return;

    int beg = rowptr[node];
    int end = rowptr[node + 1];

    float4 acc = y4[node * (DD/4) + lane];   // self loop
    for (int base = beg; base < end; base += 32) {
        int n = min(32, end - base);
        int s = (base + lane < end) ? eadj[base + lane] : 0;
#pragma unroll 4
        for (int j = 0; j < n; j++) {
            int src = __shfl_sync(0xffffffffu, s, j);
            float4 v = y4[src * (DD/4) + lane];
            acc.x += v.x; acc.y += v.y; acc.z += v.z; acc.w += v.w;
        }
    }
    float di = dinv[node];
    const float4 b = ((const float4*)bias)[lane];
    float4 o;
    o.x = fmaf(acc.x, di, b.x);
    o.y = fmaf(acc.y, di, b.y);
    o.z = fmaf(acc.z, di, b.z);
    o.w = fmaf(acc.w, di, b.w);
    out4[node * (DD/4) + lane] = o;
}

// ---------------------------------------------------------------------------
// Pooling
// ---------------------------------------------------------------------------
__device__ __forceinline__ void red_add_v4(float* addr, float4 v) {
    asm volatile("red.global.add.v4.f32 [%0], {%1, %2, %3, %4};"
                 :: "l"(addr), "f"(v.x), "f"(v.y), "f"(v.z), "f"(v.w)
                 : "memory");
}

__global__ void k_zero_pool(float4* psum, float* pcnt, int G) {
    int t = blockIdx.x * blockDim.x + threadIdx.x;
    if (t < G * (DD/4)) psum[t] = make_float4(0.f, 0.f, 0.f, 0.f);
    if (t < G) pcnt[t] = 0.f;
}

__global__ __launch_bounds__(256)
void k_pool(const float4* __restrict__ h4, const int* __restrict__ batch,
            float4* __restrict__ psum, float* __restrict__ pcnt, int N) {
    int warp = (blockIdx.x * blockDim.x + threadIdx.x) >> 5;
    int lane = threadIdx.x & 31;
    if (warp >= N) return;
    int g = batch[warp];
    float4 v = h4[warp * (DD/4) + lane];
    red_add_v4((float*)(psum + g * (DD/4) + lane), v);
    if (lane == 0) atomicAdd(&pcnt[g], 1.0f);
}

// ---------------------------------------------------------------------------
// MLP head: pooled(D) -> 100 -> 4.  One block per graph.
// ---------------------------------------------------------------------------
__global__ __launch_bounds__(128)
void k_mlp(const float4* __restrict__ psum, const float* __restrict__ pcnt,
           const float* __restrict__ w1, const float* __restrict__ b1,
           const float* __restrict__ w2, const float* __restrict__ b2,
           float* __restrict__ out, int H) {
    __shared__ float p[DD];
    __shared__ float hid[128];
    int g   = blockIdx.x;
    int tid = threadIdx.x;

    float cnt = fmaxf(pcnt[g], 1.0f);
    float inv = 1.0f / cnt;
    const float* ps = (const float*)(psum + g * (DD/4));
    p[tid] = ps[tid] * inv;
    __syncthreads();

    if (tid < H) {
        float s = b1[tid];
#pragma unroll 8
        for (int k = 0; k < DD; k++) s += p[k] * w1[k * H + tid];
        hid[tid] = fmaxf(s, 0.f);
    }
    __syncthreads();

    if (tid < 4) {
        float s = b2[tid];
        for (int j = 0; j < H; j++) s += hid[j] * w2[j * 4 + tid];
        out[g * 4 + tid] = s;
    }
}

// ---------------------------------------------------------------------------
// Launch
// ---------------------------------------------------------------------------
extern "C" void kernel_launch(void* const* d_in, const int* in_sizes, int n_in,
                              void* d_out, int out_size) {
    const float* x     = (const float*)d_in[0];
    const float* Ws    = (const float*)d_in[1];
    const float* bs    = (const float*)d_in[2];
    const float* w1    = (const float*)d_in[3];
    const float* b1    = (const float*)d_in[4];
    const float* w2    = (const float*)d_in[5];
    const float* b2    = (const float*)d_in[6];
    const int*   ei    = (const int*)d_in[7];
    const int*   batch = (const int*)d_in[8];
    float*       out   = (float*)d_out;

    const int N = in_sizes[8];          // 100000
    const int E = in_sizes[7] / 2;      // 1600000
    const int G = out_size / 4;         // 512
    const int H = in_sizes[4];          // 100

    int *cnt, *rowptr, *cur, *eadj;
    float *dinv, *pcnt;
    float4 *y, *hA, *hB, *psum;
    cudaGetSymbolAddress((void**)&cnt,    g_cnt);
    cudaGetSymbolAddress((void**)&rowptr, g_rowptr);
    cudaGetSymbolAddress((void**)&cur,    g_cur);
    cudaGetSymbolAddress((void**)&eadj,   g_eadj);
    cudaGetSymbolAddress((void**)&dinv,   g_dinv);
    cudaGetSymbolAddress((void**)&y,      g_y);
    cudaGetSymbolAddress((void**)&hA,     g_hA);
    cudaGetSymbolAddress((void**)&hB,     g_hB);
    cudaGetSymbolAddress((void**)&psum,   g_psum);
    cudaGetSymbolAddress((void**)&pcnt,   g_pcnt);

    const int T = 256;

    // CSR build + normalization
    k_zero_cnt <<<(N + T - 1) / T, T>>>(cnt, N);
    k_count    <<<(E + T - 1) / T, T>>>(ei, cnt, E);
    k_dinv     <<<(N + T - 1) / T, T>>>(cnt, dinv, N);
    k_scan     <<<1, 1024>>>(cnt, rowptr, N);
    k_copy_cur <<<(N + T - 1) / T, T>>>(rowptr, cur, N);
    k_fill     <<<(E + T - 1) / T, T>>>(ei, cur, eadj, E);

    // 4 GCN layers
    const float4* hin = (const float4*)x;
    const int gemmBlocks = (N + BM - 1) / BM;
    const int nodeWarpBlocks = (N + 7) / 8;     // 8 warps (nodes) per block
    for (int L = 0; L < 4; L++) {
        const float4* W4 = (const float4*)(Ws + (size_t)L * DD * DD);
        k_gemm<<<gemmBlocks, 256>>>(hin, W4, y, dinv, N, L > 0 ? 1 : 0);
        float4* hout = (L & 1) ? hB : hA;
        k_scatter_csr<<<nodeWarpBlocks, 256>>>(y, rowptr, eadj, dinv,
                                               bs + L * DD, hout, N);
        hin = hout;
    }

    // pooling + MLP
    k_zero_pool<<<(G * (DD/4) + T - 1) / T, T>>>(psum, pcnt, G);
    k_pool     <<<nodeWarpBlocks, 256>>>(hin, batch, psum, pcnt, N);
    k_mlp      <<<G, 128>>>(psum, pcnt, w1, b1, w2, b2, out, H);
}

// round 4
// speedup vs baseline: 1.2179x; 1.0924x over previous
#include <cuda_runtime.h>
#include <cuda_bf16.h>

// ---------------------------------------------------------------------------
// GCN_40037685134216: 4-layer GCN + mean-pool + MLP head, fp32.
// N=100000 nodes, E=1600000 edges, D=128, 512 graphs.
// R4: parallel CSR scan (3-phase), pooling fused into last-layer scatter.
//     out[c] = b + dinv[c]*( y[c] + sum_{in-edges} y[r] ),  y = dinv*(relu(h)@W)
// ---------------------------------------------------------------------------

#define MAX_N 100000
#define MAX_E 1600000
#define DD    128
#define MAX_G 512
#define SCAN_BLK 1024
#define NB ((MAX_N + SCAN_BLK - 1) / SCAN_BLK)   // 98

__device__ __align__(16) int    g_cnt [MAX_N];
__device__ __align__(16) int    g_rowptr[MAX_N + 1];
__device__ __align__(16) int    g_cur [MAX_N];
__device__ __align__(16) int    g_eadj[MAX_E];
__device__ __align__(16) float  g_dinv[MAX_N];
__device__ __align__(16) int    g_bsum[NB];
__device__ __align__(16) int    g_boff[NB];
__device__ float4 g_y  [MAX_N * (DD/4)];
__device__ float4 g_hA [MAX_N * (DD/4)];
__device__ float4 g_hB [MAX_N * (DD/4)];
__device__ float4 g_psum[MAX_G * (DD/4)];
__device__ float  g_pcnt[MAX_G];

// ---------------------------------------------------------------------------
// CSR build
// ---------------------------------------------------------------------------
__global__ void k_zero_cnt(int* cnt, int N) {
    int i = blockIdx.x * blockDim.x + threadIdx.x;
    if (i < N) cnt[i] = 0;
}

__global__ void k_count(const int* __restrict__ ei, int* cnt, int E) {
    int e = blockIdx.x * blockDim.x + threadIdx.x;
    if (e < E) atomicAdd(&cnt[ei[E + e]], 1);
}

__global__ void k_dinv(const int* __restrict__ cnt, float* dinv, int N) {
    int i = blockIdx.x * blockDim.x + threadIdx.x;
    if (i < N) dinv[i] = rsqrtf((float)cnt[i] + 1.0f);  // +1 self loop
}

// Phase 1: per-block sums of 1024-element chunks.
__global__ __launch_bounds__(256)
void k_blocksum(const int* __restrict__ cnt, int* __restrict__ bsum, int N) {
    __shared__ int red[8];
    int b = blockIdx.x, t = threadIdx.x;
    int base = b * SCAN_BLK;
    int s = 0;
#pragma unroll
    for (int j = 0; j < 4; j++) {
        int i = base + t + j * 256;
        if (i < N) s += cnt[i];
    }
#pragma unroll
    for (int off = 16; off > 0; off >>= 1)
        s += __shfl_down_sync(0xffffffffu, s, off);
    if ((t & 31) == 0) red[t >> 5] = s;
    __syncthreads();
    if (t < 8) {
        s = red[t];
#pragma unroll
        for (int off = 4; off > 0; off >>= 1)
            s += __shfl_down_sync(0xffu, s, off);
        if (t == 0) bsum[b] = s;
    }
}

// Phase 2: scan the (<=128) block sums; write rowptr[N]=E.
__global__ __launch_bounds__(128)
void k_scanbsum(const int* __restrict__ bsum, int* __restrict__ boff,
                int* __restrict__ rowptr, int nb, int N, int E) {
    __shared__ int s[128];
    int t = threadIdx.x;
    int v = (t < nb) ? bsum[t] : 0;
    s[t] = v;
    __syncthreads();
    for (int off = 1; off < 128; off <<= 1) {
        int u = (t >= off) ? s[t - off] : 0;
        __syncthreads();
        s[t] += u;
        __syncthreads();
    }
    if (t < nb) boff[t] = s[t] - v;     // exclusive
    if (t == 0) rowptr[N] = E;
}

// Phase 3: per-block scan of 1024 elements + block offset -> rowptr, cur.
__global__ __launch_bounds__(SCAN_BLK)
void k_scanblock(const int* __restrict__ cnt, const int* __restrict__ boff,
                 int* __restrict__ rowptr, int* __restrict__ cur, int N) {
    __shared__ int s[SCAN_BLK];
    int b = blockIdx.x, t = threadIdx.x;
    int i = b * SCAN_BLK + t;
    int v = (i < N) ? cnt[i] : 0;
    s[t] = v;
    __syncthreads();
    for (int off = 1; off < SCAN_BLK; off <<= 1) {
        int u = (t >= off) ? s[t - off] : 0;
        __syncthreads();
        s[t] += u;
        __syncthreads();
    }
    if (i < N) {
        int ex = boff[b] + s[t] - v;    // exclusive prefix
        rowptr[i] = ex;
        cur[i]    = ex;
    }
}

__global__ void k_fill(const int* __restrict__ ei, int* cur,
                       int* __restrict__ eadj, int E) {
    int e = blockIdx.x * blockDim.x + threadIdx.x;
    if (e < E) {
        int r = ei[e];
        int c = ei[E + e];
        int pos = atomicAdd(&cur[c], 1);
        eadj[pos] = r;
    }
}

// ---------------------------------------------------------------------------
// SGEMM: Y[M,128] = dinv[m] * ( act(A[M,128]) @ W[128,128] )
// ---------------------------------------------------------------------------
#define BM 128
#define BN 128
#define BK 16
#define TM 8
#define TN 8

__global__ __launch_bounds__(256)
void k_gemm(const float4* __restrict__ A4, const float4* __restrict__ W4,
            float4* __restrict__ Y4, const float* __restrict__ dinv,
            int M, int applyRelu) {
    __shared__ float As[BK][BM];
    __shared__ float Bs[BK][BN];

    const int tid = threadIdx.x;
    const int tx  = tid & 15;
    const int ty  = tid >> 4;
    const int m0  = blockIdx.x * BM;

    float acc[TM][TN];
#pragma unroll
    for (int i = 0; i < TM; i++)
#pragma unroll
        for (int j = 0; j < TN; j++) acc[i][j] = 0.0f;

#pragma unroll
    for (int k0 = 0; k0 < DD; k0 += BK) {
#pragma unroll
        for (int i = 0; i < 2; i++) {
            int id = tid + i * 256;
            int m  = id >> 2;
            int kq = id & 3;
            float4 v = make_float4(0.f, 0.f, 0.f, 0.f);
            int gr = m0 + m;
            if (gr < M) v = A4[gr * (DD/4) + (k0 >> 2) + kq];
            if (applyRelu) {
                v.x = fmaxf(v.x, 0.f); v.y = fmaxf(v.y, 0.f);
                v.z = fmaxf(v.z, 0.f); v.w = fmaxf(v.w, 0.f);
            }
            int kb = kq * 4;
            As[kb + 0][m] = v.x; As[kb + 1][m] = v.y;
            As[kb + 2][m] = v.z; As[kb + 3][m] = v.w;
        }
#pragma unroll
        for (int i = 0; i < 2; i++) {
            int id = tid + i * 256;
            int kk = id >> 5;
            int nq = id & 31;
            float4 v = W4[(k0 + kk) * (DD/4) + nq];
            *(float4*)&Bs[kk][nq * 4] = v;
        }
        __syncthreads();

#pragma unroll
        for (int kk = 0; kk < BK; kk++) {
            float a[TM], b[TN];
            *(float4*)&a[0] = *(const float4*)&As[kk][ty * TM];
            *(float4*)&a[4] = *(const float4*)&As[kk][ty * TM + 4];
            *(float4*)&b[0] = *(const float4*)&Bs[kk][tx * TN];
            *(float4*)&b[4] = *(const float4*)&Bs[kk][tx * TN + 4];
#pragma unroll
            for (int i = 0; i < TM; i++)
#pragma unroll
                for (int j = 0; j < TN; j++)
                    acc[i][j] += a[i] * b[j];
        }
        __syncthreads();
    }

#pragma unroll
    for (int i = 0; i < TM; i++) {
        int gr = m0 + ty * TM + i;
        if (gr < M) {
            float di = dinv[gr];
            float4 v0 = make_float4(acc[i][0] * di, acc[i][1] * di,
                                    acc[i][2] * di, acc[i][3] * di);
            float4 v1 = make_float4(acc[i][4] * di, acc[i][5] * di,
                                    acc[i][6] * di, acc[i][7] * di);
            Y4[gr * (DD/4) + (tx * TN) / 4]     = v0;
            Y4[gr * (DD/4) + (tx * TN) / 4 + 1] = v1;
        }
    }
}

// ---------------------------------------------------------------------------
// CSR scatter: one warp per node. Optionally fuse mean-pool accumulation.
// ---------------------------------------------------------------------------
__device__ __forceinline__ void red_add_v4(float* addr, float4 v) {
    asm volatile("red.global.add.v4.f32 [%0], {%1, %2, %3, %4};"
                 :: "l"(addr), "f"(v.x), "f"(v.y), "f"(v.z), "f"(v.w)
                 : "memory");
}

__global__ __launch_bounds__(256)
void k_scatter_csr(const float4* __restrict__ y4,
                   const int* __restrict__ rowptr,
                   const int* __restrict__ eadj,
                   const float* __restrict__ dinv,
                   const float* __restrict__ bias,
                   float4* __restrict__ out4,
                   const int* __restrict__ batch,   // non-null => pool mode
                   float4* __restrict__ psum, float* __restrict__ pcnt,
                   int N) {
    int node = (blockIdx.x * blockDim.x + threadIdx.x) >> 5;
    int lane = threadIdx.x & 31;
    if (node >= N) return;

    int beg = rowptr[node];
    int end = rowptr[node + 1];

    float4 acc = y4[node * (DD/4) + lane];   // self loop
    for (int base = beg; base < end; base += 32) {
        int n = min(32, end - base);
        int s = (base + lane < end) ? eadj[base + lane] : 0;
#pragma unroll 4
        for (int j = 0; j < n; j++) {
            int src = __shfl_sync(0xffffffffu, s, j);
            float4 v = y4[src * (DD/4) + lane];
            acc.x += v.x; acc.y += v.y; acc.z += v.z; acc.w += v.w;
        }
    }
    float di = dinv[node];
    const float4 b = ((const float4*)bias)[lane];
    float4 o;
    o.x = fmaf(acc.x, di, b.x);
    o.y = fmaf(acc.y, di, b.y);
    o.z = fmaf(acc.z, di, b.z);
    o.w = fmaf(acc.w, di, b.w);

    if (batch) {
        int g = batch[node];
        red_add_v4((float*)(psum + g * (DD/4) + lane), o);
        if (lane == 0) atomicAdd(&pcnt[g], 1.0f);
    } else {
        out4[node * (DD/4) + lane] = o;
    }
}

// ---------------------------------------------------------------------------
// Pool zero + MLP head
// ---------------------------------------------------------------------------
__global__ void k_zero_pool(float4* psum, float* pcnt, int G) {
    int t = blockIdx.x * blockDim.x + threadIdx.x;
    if (t < G * (DD/4)) psum[t] = make_float4(0.f, 0.f, 0.f, 0.f);
    if (t < G) pcnt[t] = 0.f;
}

__global__ __launch_bounds__(128)
void k_mlp(const float4* __restrict__ psum, const float* __restrict__ pcnt,
           const float* __restrict__ w1, const float* __restrict__ b1,
           const float* __restrict__ w2, const float* __restrict__ b2,
           float* __restrict__ out, int H) {
    __shared__ float p[DD];
    __shared__ float hid[128];
    int g   = blockIdx.x;
    int tid = threadIdx.x;

    float cnt = fmaxf(pcnt[g], 1.0f);
    float inv = 1.0f / cnt;
    const float* ps = (const float*)(psum + g * (DD/4));
    p[tid] = ps[tid] * inv;
    __syncthreads();

    if (tid < H) {
        float s = b1[tid];
#pragma unroll 8
        for (int k = 0; k < DD; k++) s += p[k] * w1[k * H + tid];
        hid[tid] = fmaxf(s, 0.f);
    }
    __syncthreads();

    if (tid < 4) {
        float s = b2[tid];
        for (int j = 0; j < H; j++) s += hid[j] * w2[j * 4 + tid];
        out[g * 4 + tid] = s;
    }
}

// ---------------------------------------------------------------------------
// Launch
// ---------------------------------------------------------------------------
extern "C" void kernel_launch(void* const* d_in, const int* in_sizes, int n_in,
                              void* d_out, int out_size) {
    const float* x     = (const float*)d_in[0];
    const float* Ws    = (const float*)d_in[1];
    const float* bs    = (const float*)d_in[2];
    const float* w1    = (const float*)d_in[3];
    const float* b1    = (const float*)d_in[4];
    const float* w2    = (const float*)d_in[5];
    const float* b2    = (const float*)d_in[6];
    const int*   ei    = (const int*)d_in[7];
    const int*   batch = (const int*)d_in[8];
    float*       out   = (float*)d_out;

    const int N = in_sizes[8];          // 100000
    const int E = in_sizes[7] / 2;      // 1600000
    const int G = out_size / 4;         // 512
    const int H = in_sizes[4];          // 100

    int *cnt, *rowptr, *cur, *eadj, *bsum, *boff;
    float *dinv, *pcnt;
    float4 *y, *hA, *hB, *psum;
    cudaGetSymbolAddress((void**)&cnt,    g_cnt);
    cudaGetSymbolAddress((void**)&rowptr, g_rowptr);
    cudaGetSymbolAddress((void**)&cur,    g_cur);
    cudaGetSymbolAddress((void**)&eadj,   g_eadj);
    cudaGetSymbolAddress((void**)&bsum,   g_bsum);
    cudaGetSymbolAddress((void**)&boff,   g_boff);
    cudaGetSymbolAddress((void**)&dinv,   g_dinv);
    cudaGetSymbolAddress((void**)&y,      g_y);
    cudaGetSymbolAddress((void**)&hA,     g_hA);
    cudaGetSymbolAddress((void**)&hB,     g_hB);
    cudaGetSymbolAddress((void**)&psum,   g_psum);
    cudaGetSymbolAddress((void**)&pcnt,   g_pcnt);

    const int T  = 256;
    const int nb = (N + SCAN_BLK - 1) / SCAN_BLK;

    // CSR build + normalization
    k_zero_cnt <<<(N + T - 1) / T, T>>>(cnt, N);
    k_count    <<<(E + T - 1) / T, T>>>(ei, cnt, E);
    k_dinv     <<<(N + T - 1) / T, T>>>(cnt, dinv, N);
    k_blocksum <<<nb, 256>>>(cnt, bsum, N);
    k_scanbsum <<<1, 128>>>(bsum, boff, rowptr, nb, N, E);
    k_scanblock<<<nb, SCAN_BLK>>>(cnt, boff, rowptr, cur, N);
    k_fill     <<<(E + T - 1) / T, T>>>(ei, cur, eadj, E);
    k_zero_pool<<<(G * (DD/4) + T - 1) / T, T>>>(psum, pcnt, G);

    // 4 GCN layers
    const float4* hin = (const float4*)x;
    const int gemmBlocks = (N + BM - 1) / BM;
    const int nodeWarpBlocks = (N + 7) / 8;
    for (int L = 0; L < 4; L++) {
        const float4* W4 = (const float4*)(Ws + (size_t)L * DD * DD);
        k_gemm<<<gemmBlocks, 256>>>(hin, W4, y, dinv, N, L > 0 ? 1 : 0);
        float4* hout = (L & 1) ? hB : hA;
        if (L < 3) {
            k_scatter_csr<<<nodeWarpBlocks, 256>>>(y, rowptr, eadj, dinv,
                                                   bs + L * DD, hout,
                                                   nullptr, nullptr, nullptr, N);
            hin = hout;
        } else {
            // last layer: fuse mean-pool accumulation, no h write
            k_scatter_csr<<<nodeWarpBlocks, 256>>>(y, rowptr, eadj, dinv,
                                                   bs + L * DD, nullptr,
                                                   batch, psum, pcnt, N);
        }
    }

    k_mlp<<<G, 128>>>(psum, pcnt, w1, b1, w2, b2, out, H);
}

// round 5
// speedup vs baseline: 2.5022x; 2.0546x over previous
#include <cuda_runtime.h>
#include <cuda_bf16.h>
#include <cstdint>

// ---------------------------------------------------------------------------
// GCN_40037685134216: 4-layer GCN + mean-pool + MLP head, fp32.
// R5: GEMM moved to tensor cores (mma.sync m16n8k8 tf32, 3xTF32 split for
//     fp32-grade accuracy). Everything else as R4.
// ---------------------------------------------------------------------------

#define MAX_N 100000
#define MAX_E 1600000
#define DD    128
#define MAX_G 512
#define SCAN_BLK 1024
#define NB ((MAX_N + SCAN_BLK - 1) / SCAN_BLK)   // 98

__device__ __align__(16) int    g_cnt [MAX_N];
__device__ __align__(16) int    g_rowptr[MAX_N + 1];
__device__ __align__(16) int    g_cur [MAX_N];
__device__ __align__(16) int    g_eadj[MAX_E];
__device__ __align__(16) float  g_dinv[MAX_N];
__device__ __align__(16) int    g_bsum[NB];
__device__ __align__(16) int    g_boff[NB];
__device__ float4 g_y  [MAX_N * (DD/4)];
__device__ float4 g_hA [MAX_N * (DD/4)];
__device__ float4 g_hB [MAX_N * (DD/4)];
__device__ float4 g_psum[MAX_G * (DD/4)];
__device__ float  g_pcnt[MAX_G];

// ---------------------------------------------------------------------------
// CSR build
// ---------------------------------------------------------------------------
__global__ void k_zero_cnt(int* cnt, int N) {
    int i = blockIdx.x * blockDim.x + threadIdx.x;
    if (i < N) cnt[i] = 0;
}

__global__ void k_count(const int* __restrict__ ei, int* cnt, int E) {
    int e = blockIdx.x * blockDim.x + threadIdx.x;
    if (e < E) atomicAdd(&cnt[ei[E + e]], 1);
}

__global__ void k_dinv(const int* __restrict__ cnt, float* dinv, int N) {
    int i = blockIdx.x * blockDim.x + threadIdx.x;
    if (i < N) dinv[i] = rsqrtf((float)cnt[i] + 1.0f);  // +1 self loop
}

__global__ __launch_bounds__(256)
void k_blocksum(const int* __restrict__ cnt, int* __restrict__ bsum, int N) {
    __shared__ int red[8];
    int b = blockIdx.x, t = threadIdx.x;
    int base = b * SCAN_BLK;
    int s = 0;
#pragma unroll
    for (int j = 0; j < 4; j++) {
        int i = base + t + j * 256;
        if (i < N) s += cnt[i];
    }
#pragma unroll
    for (int off = 16; off > 0; off >>= 1)
        s += __shfl_down_sync(0xffffffffu, s, off);
    if ((t & 31) == 0) red[t >> 5] = s;
    __syncthreads();
    if (t < 8) {
        s = red[t];
#pragma unroll
        for (int off = 4; off > 0; off >>= 1)
            s += __shfl_down_sync(0xffu, s, off);
        if (t == 0) bsum[b] = s;
    }
}

__global__ __launch_bounds__(128)
void k_scanbsum(const int* __restrict__ bsum, int* __restrict__ boff,
                int* __restrict__ rowptr, int nb, int N, int E) {
    __shared__ int s[128];
    int t = threadIdx.x;
    int v = (t < nb) ? bsum[t] : 0;
    s[t] = v;
    __syncthreads();
    for (int off = 1; off < 128; off <<= 1) {
        int u = (t >= off) ? s[t - off] : 0;
        __syncthreads();
        s[t] += u;
        __syncthreads();
    }
    if (t < nb) boff[t] = s[t] - v;
    if (t == 0) rowptr[N] = E;
}

__global__ __launch_bounds__(SCAN_BLK)
void k_scanblock(const int* __restrict__ cnt, const int* __restrict__ boff,
                 int* __restrict__ rowptr, int* __restrict__ cur, int N) {
    __shared__ int s[SCAN_BLK];
    int b = blockIdx.x, t = threadIdx.x;
    int i = b * SCAN_BLK + t;
    int v = (i < N) ? cnt[i] : 0;
    s[t] = v;
    __syncthreads();
    for (int off = 1; off < SCAN_BLK; off <<= 1) {
        int u = (t >= off) ? s[t - off] : 0;
        __syncthreads();
        s[t] += u;
        __syncthreads();
    }
    if (i < N) {
        int ex = boff[b] + s[t] - v;
        rowptr[i] = ex;
        cur[i]    = ex;
    }
}

__global__ void k_fill(const int* __restrict__ ei, int* cur,
                       int* __restrict__ eadj, int E) {
    int e = blockIdx.x * blockDim.x + threadIdx.x;
    if (e < E) {
        int r = ei[e];
        int c = ei[E + e];
        int pos = atomicAdd(&cur[c], 1);
        eadj[pos] = r;
    }
}

// ---------------------------------------------------------------------------
// TF32 tensor-core GEMM: Y[M,128] = dinv[m] * ( act(A[M,128]) @ W[128,128] )
// 3xTF32 split: a=ah+al, b=bh+bl; acc += ah*bl + al*bh + ah*bh.
// BM=128, BN=128 (full), BK=16 chunks. 256 threads = 8 warps (4 M-bands x 2 N-bands).
// ---------------------------------------------------------------------------
#define BM 128
#define PA 20    // A smem pitch (f32): conflict-free for frag loads
#define PW 136   // W smem pitch (f32): conflict-free for frag loads

__device__ __forceinline__ uint32_t f2tf32(float x) {
    uint32_t r;
    asm("cvt.rna.tf32.f32 %0, %1;" : "=r"(r) : "f"(x));
    return r;
}

__device__ __forceinline__ void split_tf32(float x, uint32_t& hi, uint32_t& lo) {
    hi = f2tf32(x);
    lo = f2tf32(x - __uint_as_float(hi));
}

__device__ __forceinline__ void mma_tf32(float* c, const uint32_t* a, const uint32_t* b) {
    asm volatile("mma.sync.aligned.m16n8k8.row.col.f32.tf32.tf32.f32 "
                 "{%0,%1,%2,%3}, {%4,%5,%6,%7}, {%8,%9}, {%0,%1,%2,%3};"
                 : "+f"(c[0]), "+f"(c[1]), "+f"(c[2]), "+f"(c[3])
                 : "r"(a[0]), "r"(a[1]), "r"(a[2]), "r"(a[3]),
                   "r"(b[0]), "r"(b[1]));
}

__global__ __launch_bounds__(256)
void k_gemm_tf32(const float4* __restrict__ A4, const float4* __restrict__ W4,
                 float* __restrict__ Y, const float* __restrict__ dinv,
                 int M, int applyRelu) {
    __shared__ uint32_t Ah[BM * PA], Al[BM * PA];
    __shared__ uint32_t Wh[16 * PW], Wl[16 * PW];

    const int tid  = threadIdx.x;
    const int lane = tid & 31;
    const int wid  = tid >> 5;
    const int wm   = wid & 3;        // M band (32 rows)
    const int wn   = wid >> 2;       // N band (64 cols)
    const int grp  = lane >> 2;
    const int tig  = lane & 3;
    const int m0   = blockIdx.x * BM;

    float acc[2][8][4];
#pragma unroll
    for (int f = 0; f < 2; f++)
#pragma unroll
        for (int g = 0; g < 8; g++)
#pragma unroll
            for (int j = 0; j < 4; j++) acc[f][g][j] = 0.0f;

    for (int k0 = 0; k0 < DD; k0 += 16) {
        // --- load A chunk [128 x 16] with relu, split hi/lo ---
#pragma unroll
        for (int i = 0; i < 2; i++) {
            int id  = tid + i * 256;          // 0..511
            int row = id >> 2;                // 0..127
            int q   = id & 3;                 // float4 within 16-k
            float4 v = make_float4(0.f, 0.f, 0.f, 0.f);
            int gr = m0 + row;
            if (gr < M) v = A4[gr * (DD/4) + (k0 >> 2) + q];
            if (applyRelu) {
                v.x = fmaxf(v.x, 0.f); v.y = fmaxf(v.y, 0.f);
                v.z = fmaxf(v.z, 0.f); v.w = fmaxf(v.w, 0.f);
            }
            uint32_t h0, l0, h1, l1, h2, l2, h3, l3;
            split_tf32(v.x, h0, l0); split_tf32(v.y, h1, l1);
            split_tf32(v.z, h2, l2); split_tf32(v.w, h3, l3);
            int base = row * PA + q * 4;
            Ah[base + 0] = h0; Ah[base + 1] = h1; Ah[base + 2] = h2; Ah[base + 3] = h3;
            Al[base + 0] = l0; Al[base + 1] = l1; Al[base + 2] = l2; Al[base + 3] = l3;
        }
        // --- load W chunk [16 x 128], split hi/lo ---
#pragma unroll
        for (int i = 0; i < 2; i++) {
            int id = tid + i * 256;
            int kk = id >> 5;                 // 0..15
            int nq = id & 31;                 // 0..31 float4 cols
            float4 v = W4[(k0 + kk) * (DD/4) + nq];
            uint32_t h0, l0, h1, l1, h2, l2, h3, l3;
            split_tf32(v.x, h0, l0); split_tf32(v.y, h1, l1);
            split_tf32(v.z, h2, l2); split_tf32(v.w, h3, l3);
            int base = kk * PW + nq * 4;
            Wh[base + 0] = h0; Wh[base + 1] = h1; Wh[base + 2] = h2; Wh[base + 3] = h3;
            Wl[base + 0] = l0; Wl[base + 1] = l1; Wl[base + 2] = l2; Wl[base + 3] = l3;
        }
        __syncthreads();

#pragma unroll
        for (int kk = 0; kk < 16; kk += 8) {
            // A fragments (2 x m16k8)
            uint32_t ah[2][4], al[2][4];
#pragma unroll
            for (int f = 0; f < 2; f++) {
                int r0 = wm * 32 + f * 16 + grp;
                ah[f][0] = Ah[r0 * PA + kk + tig];
                ah[f][1] = Ah[(r0 + 8) * PA + kk + tig];
                ah[f][2] = Ah[r0 * PA + kk + tig + 4];
                ah[f][3] = Ah[(r0 + 8) * PA + kk + tig + 4];
                al[f][0] = Al[r0 * PA + kk + tig];
                al[f][1] = Al[(r0 + 8) * PA + kk + tig];
                al[f][2] = Al[r0 * PA + kk + tig + 4];
                al[f][3] = Al[(r0 + 8) * PA + kk + tig + 4];
            }
            // B fragments (8 x k8n8)
            uint32_t bh[8][2], bl[8][2];
#pragma unroll
            for (int g = 0; g < 8; g++) {
                int n = wn * 64 + g * 8 + grp;
                bh[g][0] = Wh[(kk + tig) * PW + n];
                bh[g][1] = Wh[(kk + tig + 4) * PW + n];
                bl[g][0] = Wl[(kk + tig) * PW + n];
                bl[g][1] = Wl[(kk + tig + 4) * PW + n];
            }
#pragma unroll
            for (int f = 0; f < 2; f++)
#pragma unroll
                for (int g = 0; g < 8; g++) {
                    mma_tf32(acc[f][g], ah[f], bl[g]);
                    mma_tf32(acc[f][g], al[f], bh[g]);
                    mma_tf32(acc[f][g], ah[f], bh[g]);
                }
        }
        __syncthreads();
    }

    // Epilogue: scale by dinv[row], store float2 pairs.
#pragma unroll
    for (int f = 0; f < 2; f++) {
        int r0 = m0 + wm * 32 + f * 16 + grp;
        int r1 = r0 + 8;
        float d0 = (r0 < M) ? dinv[r0] : 0.f;
        float d1 = (r1 < M) ? dinv[r1] : 0.f;
#pragma unroll
        for (int g = 0; g < 8; g++) {
            int c = wn * 64 + g * 8 + tig * 2;
            if (r0 < M) {
                float2 v = make_float2(acc[f][g][0] * d0, acc[f][g][1] * d0);
                *(float2*)&Y[(size_t)r0 * DD + c] = v;
            }
            if (r1 < M) {
                float2 v = make_float2(acc[f][g][2] * d1, acc[f][g][3] * d1);
                *(float2*)&Y[(size_t)r1 * DD + c] = v;
            }
        }
    }
}

// ---------------------------------------------------------------------------
// CSR scatter: one warp per node. Optionally fuse mean-pool accumulation.
// ---------------------------------------------------------------------------
__device__ __forceinline__ void red_add_v4(float* addr, float4 v) {
    asm volatile("red.global.add.v4.f32 [%0], {%1, %2, %3, %4};"
                 :: "l"(addr), "f"(v.x), "f"(v.y), "f"(v.z), "f"(v.w)
                 : "memory");
}

__global__ __launch_bounds__(256)
void k_scatter_csr(const float4* __restrict__ y4,
                   const int* __restrict__ rowptr,
                   const int* __restrict__ eadj,
                   const float* __restrict__ dinv,
                   const float* __restrict__ bias,
                   float4* __restrict__ out4,
                   const int* __restrict__ batch,   // non-null => pool mode
                   float4* __restrict__ psum, float* __restrict__ pcnt,
                   int N) {
    int node = (blockIdx.x * blockDim.x + threadIdx.x) >> 5;
    int lane = threadIdx.x & 31;
    if (node >= N) return;

    int beg = rowptr[node];
    int end = rowptr[node + 1];

    float4 acc = y4[node * (DD/4) + lane];   // self loop
    for (int base = beg; base < end; base += 32) {
        int n = min(32, end - base);
        int s = (base + lane < end) ? eadj[base + lane] : 0;
#pragma unroll 4
        for (int j = 0; j < n; j++) {
            int src = __shfl_sync(0xffffffffu, s, j);
            float4 v = y4[src * (DD/4) + lane];
            acc.x += v.x; acc.y += v.y; acc.z += v.z; acc.w += v.w;
        }
    }
    float di = dinv[node];
    const float4 b = ((const float4*)bias)[lane];
    float4 o;
    o.x = fmaf(acc.x, di, b.x);
    o.y = fmaf(acc.y, di, b.y);
    o.z = fmaf(acc.z, di, b.z);
    o.w = fmaf(acc.w, di, b.w);

    if (batch) {
        int g = batch[node];
        red_add_v4((float*)(psum + g * (DD/4) + lane), o);
        if (lane == 0) atomicAdd(&pcnt[g], 1.0f);
    } else {
        out4[node * (DD/4) + lane] = o;
    }
}

// ---------------------------------------------------------------------------
// Pool zero + MLP head
// ---------------------------------------------------------------------------
__global__ void k_zero_pool(float4* psum, float* pcnt, int G) {
    int t = blockIdx.x * blockDim.x + threadIdx.x;
    if (t < G * (DD/4)) psum[t] = make_float4(0.f, 0.f, 0.f, 0.f);
    if (t < G) pcnt[t] = 0.f;
}

__global__ __launch_bounds__(128)
void k_mlp(const float4* __restrict__ psum, const float* __restrict__ pcnt,
           const float* __restrict__ w1, const float* __restrict__ b1,
           const float* __restrict__ w2, const float* __restrict__ b2,
           float* __restrict__ out, int H) {
    __shared__ float p[DD];
    __shared__ float hid[128];
    int g   = blockIdx.x;
    int tid = threadIdx.x;

    float cnt = fmaxf(pcnt[g], 1.0f);
    float inv = 1.0f / cnt;
    const float* ps = (const float*)(psum + g * (DD/4));
    p[tid] = ps[tid] * inv;
    __syncthreads();

    if (tid < H) {
        float s = b1[tid];
#pragma unroll 8
        for (int k = 0; k < DD; k++) s += p[k] * w1[k * H + tid];
        hid[tid] = fmaxf(s, 0.f);
    }
    __syncthreads();

    if (tid < 4) {
        float s = b2[tid];
        for (int j = 0; j < H; j++) s += hid[j] * w2[j * 4 + tid];
        out[g * 4 + tid] = s;
    }
}

// ---------------------------------------------------------------------------
// Launch
// ---------------------------------------------------------------------------
extern "C" void kernel_launch(void* const* d_in, const int* in_sizes, int n_in,
                              void* d_out, int out_size) {
    const float* x     = (const float*)d_in[0];
    const float* Ws    = (const float*)d_in[1];
    const float* bs    = (const float*)d_in[2];
    const float* w1    = (const float*)d_in[3];
    const float* b1    = (const float*)d_in[4];
    const float* w2    = (const float*)d_in[5];
    const float* b2    = (const float*)d_in[6];
    const int*   ei    = (const int*)d_in[7];
    const int*   batch = (const int*)d_in[8];
    float*       out   = (float*)d_out;

    const int N = in_sizes[8];          // 100000
    const int E = in_sizes[7] / 2;      // 1600000
    const int G = out_size / 4;         // 512
    const int H = in_sizes[4];          // 100

    int *cnt, *rowptr, *cur, *eadj, *bsum, *boff;
    float *dinv, *pcnt;
    float4 *y, *hA, *hB, *psum;
    cudaGetSymbolAddress((void**)&cnt,    g_cnt);
    cudaGetSymbolAddress((void**)&rowptr, g_rowptr);
    cudaGetSymbolAddress((void**)&cur,    g_cur);
    cudaGetSymbolAddress((void**)&eadj,   g_eadj);
    cudaGetSymbolAddress((void**)&bsum,   g_bsum);
    cudaGetSymbolAddress((void**)&boff,   g_boff);
    cudaGetSymbolAddress((void**)&dinv,   g_dinv);
    cudaGetSymbolAddress((void**)&y,      g_y);
    cudaGetSymbolAddress((void**)&hA,     g_hA);
    cudaGetSymbolAddress((void**)&hB,     g_hB);
    cudaGetSymbolAddress((void**)&psum,   g_psum);
    cudaGetSymbolAddress((void**)&pcnt,   g_pcnt);

    const int T  = 256;
    const int nb = (N + SCAN_BLK - 1) / SCAN_BLK;

    // CSR build + normalization
    k_zero_cnt <<<(N + T - 1) / T, T>>>(cnt, N);
    k_count    <<<(E + T - 1) / T, T>>>(ei, cnt, E);
    k_dinv     <<<(N + T - 1) / T, T>>>(cnt, dinv, N);
    k_blocksum <<<nb, 256>>>(cnt, bsum, N);
    k_scanbsum <<<1, 128>>>(bsum, boff, rowptr, nb, N, E);
    k_scanblock<<<nb, SCAN_BLK>>>(cnt, boff, rowptr, cur, N);
    k_fill     <<<(E + T - 1) / T, T>>>(ei, cur, eadj, E);
    k_zero_pool<<<(G * (DD/4) + T - 1) / T, T>>>(psum, pcnt, G);

    // 4 GCN layers
    const float4* hin = (const float4*)x;
    const int gemmBlocks = (N + BM - 1) / BM;
    const int nodeWarpBlocks = (N + 7) / 8;
    for (int L = 0; L < 4; L++) {
        const float4* W4 = (const float4*)(Ws + (size_t)L * DD * DD);
        k_gemm_tf32<<<gemmBlocks, 256>>>(hin, W4, (float*)y, dinv, N, L > 0 ? 1 : 0);
        float4* hout = (L & 1) ? hB : hA;
        if (L < 3) {
            k_scatter_csr<<<nodeWarpBlocks, 256>>>(y, rowptr, eadj, dinv,
                                                   bs + L * DD, hout,
                                                   nullptr, nullptr, nullptr, N);
            hin = hout;
        } else {
            k_scatter_csr<<<nodeWarpBlocks, 256>>>(y, rowptr, eadj, dinv,
                                                   bs + L * DD, nullptr,
                                                   batch, psum, pcnt, N);
        }
    }

    k_mlp<<<G, 128>>>(psum, pcnt, w1, b1, w2, b2, out, H);
}

// round 6
// speedup vs baseline: 2.6350x; 1.0530x over previous
#include <cuda_runtime.h>
#include <cuda_fp16.h>
#include <cstdint>

// ---------------------------------------------------------------------------
// GCN_40037685134216: 4-layer GCN + mean-pool + MLP head, fp32.
// R6: message tensor y stored in fp16 (half2) -> halves scatter L2 traffic.
//     GEMM (3xTF32 tensor core) epilogue writes half2; gather accumulates fp32.
// ---------------------------------------------------------------------------

#define MAX_N 100000
#define MAX_E 1600000
#define DD    128
#define MAX_G 512
#define SCAN_BLK 1024
#define NB ((MAX_N + SCAN_BLK - 1) / SCAN_BLK)   // 98

__device__ __align__(16) int    g_cnt [MAX_N];
__device__ __align__(16) int    g_rowptr[MAX_N + 1];
__device__ __align__(16) int    g_cur [MAX_N];
__device__ __align__(16) int    g_eadj[MAX_E];
__device__ __align__(16) float  g_dinv[MAX_N];
__device__ __align__(16) int    g_bsum[NB];
__device__ __align__(16) int    g_boff[NB];
__device__ __align__(16) __half2 g_y [MAX_N * (DD/2)];   // fp16 messages
__device__ float4 g_hA [MAX_N * (DD/4)];
__device__ float4 g_hB [MAX_N * (DD/4)];
__device__ float4 g_psum[MAX_G * (DD/4)];
__device__ float  g_pcnt[MAX_G];

// ---------------------------------------------------------------------------
// CSR build
// ---------------------------------------------------------------------------
__global__ void k_zero_cnt(int* cnt, int N) {
    int i = blockIdx.x * blockDim.x + threadIdx.x;
    if (i < N) cnt[i] = 0;
}

__global__ void k_count(const int* __restrict__ ei, int* cnt, int E) {
    int e = blockIdx.x * blockDim.x + threadIdx.x;
    if (e < E) atomicAdd(&cnt[ei[E + e]], 1);
}

__global__ void k_dinv(const int* __restrict__ cnt, float* dinv, int N) {
    int i = blockIdx.x * blockDim.x + threadIdx.x;
    if (i < N) dinv[i] = rsqrtf((float)cnt[i] + 1.0f);  // +1 self loop
}

__global__ __launch_bounds__(256)
void k_blocksum(const int* __restrict__ cnt, int* __restrict__ bsum, int N) {
    __shared__ int red[8];
    int b = blockIdx.x, t = threadIdx.x;
    int base = b * SCAN_BLK;
    int s = 0;
#pragma unroll
    for (int j = 0; j < 4; j++) {
        int i = base + t + j * 256;
        if (i < N) s += cnt[i];
    }
#pragma unroll
    for (int off = 16; off > 0; off >>= 1)
        s += __shfl_down_sync(0xffffffffu, s, off);
    if ((t & 31) == 0) red[t >> 5] = s;
    __syncthreads();
    if (t < 8) {
        s = red[t];
#pragma unroll
        for (int off = 4; off > 0; off >>= 1)
            s += __shfl_down_sync(0xffu, s, off);
        if (t == 0) bsum[b] = s;
    }
}

__global__ __launch_bounds__(128)
void k_scanbsum(const int* __restrict__ bsum, int* __restrict__ boff,
                int* __restrict__ rowptr, int nb, int N, int E) {
    __shared__ int s[128];
    int t = threadIdx.x;
    int v = (t < nb) ? bsum[t] : 0;
    s[t] = v;
    __syncthreads();
    for (int off = 1; off < 128; off <<= 1) {
        int u = (t >= off) ? s[t - off] : 0;
        __syncthreads();
        s[t] += u;
        __syncthreads();
    }
    if (t < nb) boff[t] = s[t] - v;
    if (t == 0) rowptr[N] = E;
}

__global__ __launch_bounds__(SCAN_BLK)
void k_scanblock(const int* __restrict__ cnt, const int* __restrict__ boff,
                 int* __restrict__ rowptr, int* __restrict__ cur, int N) {
    __shared__ int s[SCAN_BLK];
    int b = blockIdx.x, t = threadIdx.x;
    int i = b * SCAN_BLK + t;
    int v = (i < N) ? cnt[i] : 0;
    s[t] = v;
    __syncthreads();
    for (int off = 1; off < SCAN_BLK; off <<= 1) {
        int u = (t >= off) ? s[t - off] : 0;
        __syncthreads();
        s[t] += u;
        __syncthreads();
    }
    if (i < N) {
        int ex = boff[b] + s[t] - v;
        rowptr[i] = ex;
        cur[i]    = ex;
    }
}

__global__ void k_fill(const int* __restrict__ ei, int* cur,
                       int* __restrict__ eadj, int E) {
    int e = blockIdx.x * blockDim.x + threadIdx.x;
    if (e < E) {
        int r = ei[e];
        int c = ei[E + e];
        int pos = atomicAdd(&cur[c], 1);
        eadj[pos] = r;
    }
}

// ---------------------------------------------------------------------------
// TF32 tensor-core GEMM: Y[M,128] = fp16( dinv[m] * ( act(A[M,128]) @ W ) )
// 3xTF32 split. 256 threads = 8 warps (4 M-bands x 2 N-bands).
// ---------------------------------------------------------------------------
#define BM 128
#define PA 20
#define PW 136

__device__ __forceinline__ uint32_t f2tf32(float x) {
    uint32_t r;
    asm("cvt.rna.tf32.f32 %0, %1;" : "=r"(r) : "f"(x));
    return r;
}

__device__ __forceinline__ void split_tf32(float x, uint32_t& hi, uint32_t& lo) {
    hi = f2tf32(x);
    lo = f2tf32(x - __uint_as_float(hi));
}

__device__ __forceinline__ void mma_tf32(float* c, const uint32_t* a, const uint32_t* b) {
    asm volatile("mma.sync.aligned.m16n8k8.row.col.f32.tf32.tf32.f32 "
                 "{%0,%1,%2,%3}, {%4,%5,%6,%7}, {%8,%9}, {%0,%1,%2,%3};"
                 : "+f"(c[0]), "+f"(c[1]), "+f"(c[2]), "+f"(c[3])
                 : "r"(a[0]), "r"(a[1]), "r"(a[2]), "r"(a[3]),
                   "r"(b[0]), "r"(b[1]));
}

__global__ __launch_bounds__(256)
void k_gemm_tf32(const float4* __restrict__ A4, const float4* __restrict__ W4,
                 __half2* __restrict__ Y2, const float* __restrict__ dinv,
                 int M, int applyRelu) {
    __shared__ uint32_t Ah[BM * PA], Al[BM * PA];
    __shared__ uint32_t Wh[16 * PW], Wl[16 * PW];

    const int tid  = threadIdx.x;
    const int lane = tid & 31;
    const int wid  = tid >> 5;
    const int wm   = wid & 3;
    const int wn   = wid >> 2;
    const int grp  = lane >> 2;
    const int tig  = lane & 3;
    const int m0   = blockIdx.x * BM;

    float acc[2][8][4];
#pragma unroll
    for (int f = 0; f < 2; f++)
#pragma unroll
        for (int g = 0; g < 8; g++)
#pragma unroll
            for (int j = 0; j < 4; j++) acc[f][g][j] = 0.0f;

    for (int k0 = 0; k0 < DD; k0 += 16) {
#pragma unroll
        for (int i = 0; i < 2; i++) {
            int id  = tid + i * 256;
            int row = id >> 2;
            int q   = id & 3;
            float4 v = make_float4(0.f, 0.f, 0.f, 0.f);
            int gr = m0 + row;
            if (gr < M) v = A4[gr * (DD/4) + (k0 >> 2) + q];
            if (applyRelu) {
                v.x = fmaxf(v.x, 0.f); v.y = fmaxf(v.y, 0.f);
                v.z = fmaxf(v.z, 0.f); v.w = fmaxf(v.w, 0.f);
            }
            uint32_t h0, l0, h1, l1, h2, l2, h3, l3;
            split_tf32(v.x, h0, l0); split_tf32(v.y, h1, l1);
            split_tf32(v.z, h2, l2); split_tf32(v.w, h3, l3);
            int base = row * PA + q * 4;
            Ah[base + 0] = h0; Ah[base + 1] = h1; Ah[base + 2] = h2; Ah[base + 3] = h3;
            Al[base + 0] = l0; Al[base + 1] = l1; Al[base + 2] = l2; Al[base + 3] = l3;
        }
#pragma unroll
        for (int i = 0; i < 2; i++) {
            int id = tid + i * 256;
            int kk = id >> 5;
            int nq = id & 31;
            float4 v = W4[(k0 + kk) * (DD/4) + nq];
            uint32_t h0, l0, h1, l1, h2, l2, h3, l3;
            split_tf32(v.x, h0, l0); split_tf32(v.y, h1, l1);
            split_tf32(v.z, h2, l2); split_tf32(v.w, h3, l3);
            int base = kk * PW + nq * 4;
            Wh[base + 0] = h0; Wh[base + 1] = h1; Wh[base + 2] = h2; Wh[base + 3] = h3;
            Wl[base + 0] = l0; Wl[base + 1] = l1; Wl[base + 2] = l2; Wl[base + 3] = l3;
        }
        __syncthreads();

#pragma unroll
        for (int kk = 0; kk < 16; kk += 8) {
            uint32_t ah[2][4], al[2][4];
#pragma unroll
            for (int f = 0; f < 2; f++) {
                int r0 = wm * 32 + f * 16 + grp;
                ah[f][0] = Ah[r0 * PA + kk + tig];
                ah[f][1] = Ah[(r0 + 8) * PA + kk + tig];
                ah[f][2] = Ah[r0 * PA + kk + tig + 4];
                ah[f][3] = Ah[(r0 + 8) * PA + kk + tig + 4];
                al[f][0] = Al[r0 * PA + kk + tig];
                al[f][1] = Al[(r0 + 8) * PA + kk + tig];
                al[f][2] = Al[r0 * PA + kk + tig + 4];
                al[f][3] = Al[(r0 + 8) * PA + kk + tig + 4];
            }
            uint32_t bh[8][2], bl[8][2];
#pragma unroll
            for (int g = 0; g < 8; g++) {
                int n = wn * 64 + g * 8 + grp;
                bh[g][0] = Wh[(kk + tig) * PW + n];
                bh[g][1] = Wh[(kk + tig + 4) * PW + n];
                bl[g][0] = Wl[(kk + tig) * PW + n];
                bl[g][1] = Wl[(kk + tig + 4) * PW + n];
            }
#pragma unroll
            for (int f = 0; f < 2; f++)
#pragma unroll
                for (int g = 0; g < 8; g++) {
                    mma_tf32(acc[f][g], ah[f], bl[g]);
                    mma_tf32(acc[f][g], al[f], bh[g]);
                    mma_tf32(acc[f][g], ah[f], bh[g]);
                }
        }
        __syncthreads();
    }

    // Epilogue: scale by dinv[row], convert to half2, store.
#pragma unroll
    for (int f = 0; f < 2; f++) {
        int r0 = m0 + wm * 32 + f * 16 + grp;
        int r1 = r0 + 8;
        float d0 = (r0 < M) ? dinv[r0] : 0.f;
        float d1 = (r1 < M) ? dinv[r1] : 0.f;
#pragma unroll
        for (int g = 0; g < 8; g++) {
            int c = wn * 64 + g * 8 + tig * 2;   // even
            if (r0 < M)
                Y2[(size_t)r0 * (DD/2) + (c >> 1)] =
                    __floats2half2_rn(acc[f][g][0] * d0, acc[f][g][1] * d0);
            if (r1 < M)
                Y2[(size_t)r1 * (DD/2) + (c >> 1)] =
                    __floats2half2_rn(acc[f][g][2] * d1, acc[f][g][3] * d1);
        }
    }
}

// ---------------------------------------------------------------------------
// CSR scatter: one warp per node; y in fp16 (uint2 = 4 halves per lane).
// out[c] = bias + dinv[c] * ( y[c] + sum_{in-edges} y[src] )
// ---------------------------------------------------------------------------
__device__ __forceinline__ void red_add_v4(float* addr, float4 v) {
    asm volatile("red.global.add.v4.f32 [%0], {%1, %2, %3, %4};"
                 :: "l"(addr), "f"(v.x), "f"(v.y), "f"(v.z), "f"(v.w)
                 : "memory");
}

__device__ __forceinline__ void acc_half4(float4& acc, uint2 raw) {
    __half2 h01 = *reinterpret_cast<__half2*>(&raw.x);
    __half2 h23 = *reinterpret_cast<__half2*>(&raw.y);
    float2 f01 = __half22float2(h01);
    float2 f23 = __half22float2(h23);
    acc.x += f01.x; acc.y += f01.y; acc.z += f23.x; acc.w += f23.y;
}

__global__ __launch_bounds__(256)
void k_scatter_csr(const uint2* __restrict__ y2,   // [N][32] uint2 (=4 halves)
                   const int* __restrict__ rowptr,
                   const int* __restrict__ eadj,
                   const float* __restrict__ dinv,
                   const float* __restrict__ bias,
                   float4* __restrict__ out4,
                   const int* __restrict__ batch,   // non-null => pool mode
                   float4* __restrict__ psum, float* __restrict__ pcnt,
                   int N) {
    int node = (blockIdx.x * blockDim.x + threadIdx.x) >> 5;
    int lane = threadIdx.x & 31;
    if (node >= N) return;

    int beg = rowptr[node];
    int end = rowptr[node + 1];

    float4 acc = make_float4(0.f, 0.f, 0.f, 0.f);
    acc_half4(acc, y2[(size_t)node * 32 + lane]);   // self loop
    for (int base = beg; base < end; base += 32) {
        int n = min(32, end - base);
        int s = (base + lane < end) ? eadj[base + lane] : 0;
#pragma unroll 4
        for (int j = 0; j < n; j++) {
            int src = __shfl_sync(0xffffffffu, s, j);
            acc_half4(acc, y2[(size_t)src * 32 + lane]);
        }
    }
    float di = dinv[node];
    const float4 b = ((const float4*)bias)[lane];
    float4 o;
    o.x = fmaf(acc.x, di, b.x);
    o.y = fmaf(acc.y, di, b.y);
    o.z = fmaf(acc.z, di, b.z);
    o.w = fmaf(acc.w, di, b.w);

    if (batch) {
        int g = batch[node];
        red_add_v4((float*)(psum + g * (DD/4) + lane), o);
        if (lane == 0) atomicAdd(&pcnt[g], 1.0f);
    } else {
        out4[(size_t)node * (DD/4) + lane] = o;
    }
}

// ---------------------------------------------------------------------------
// Pool zero + MLP head
// ---------------------------------------------------------------------------
__global__ void k_zero_pool(float4* psum, float* pcnt, int G) {
    int t = blockIdx.x * blockDim.x + threadIdx.x;
    if (t < G * (DD/4)) psum[t] = make_float4(0.f, 0.f, 0.f, 0.f);
    if (t < G) pcnt[t] = 0.f;
}

__global__ __launch_bounds__(128)
void k_mlp(const float4* __restrict__ psum, const float* __restrict__ pcnt,
           const float* __restrict__ w1, const float* __restrict__ b1,
           const float* __restrict__ w2, const float* __restrict__ b2,
           float* __restrict__ out, int H) {
    __shared__ float p[DD];
    __shared__ float hid[128];
    int g   = blockIdx.x;
    int tid = threadIdx.x;

    float cnt = fmaxf(pcnt[g], 1.0f);
    float inv = 1.0f / cnt;
    const float* ps = (const float*)(psum + g * (DD/4));
    p[tid] = ps[tid] * inv;
    __syncthreads();

    if (tid < H) {
        float s = b1[tid];
#pragma unroll 8
        for (int k = 0; k < DD; k++) s += p[k] * w1[k * H + tid];
        hid[tid] = fmaxf(s, 0.f);
    }
    __syncthreads();

    if (tid < 4) {
        float s = b2[tid];
        for (int j = 0; j < H; j++) s += hid[j] * w2[j * 4 + tid];
        out[g * 4 + tid] = s;
    }
}

// ---------------------------------------------------------------------------
// Launch
// ---------------------------------------------------------------------------
extern "C" void kernel_launch(void* const* d_in, const int* in_sizes, int n_in,
                              void* d_out, int out_size) {
    const float* x     = (const float*)d_in[0];
    const float* Ws    = (const float*)d_in[1];
    const float* bs    = (const float*)d_in[2];
    const float* w1    = (const float*)d_in[3];
    const float* b1    = (const float*)d_in[4];
    const float* w2    = (const float*)d_in[5];
    const float* b2    = (const float*)d_in[6];
    const int*   ei    = (const int*)d_in[7];
    const int*   batch = (const int*)d_in[8];
    float*       out   = (float*)d_out;

    const int N = in_sizes[8];          // 100000
    const int E = in_sizes[7] / 2;      // 1600000
    const int G = out_size / 4;         // 512
    const int H = in_sizes[4];          // 100

    int *cnt, *rowptr, *cur, *eadj, *bsum, *boff;
    float *dinv, *pcnt;
    __half2* y;
    float4 *hA, *hB, *psum;
    cudaGetSymbolAddress((void**)&cnt,    g_cnt);
    cudaGetSymbolAddress((void**)&rowptr, g_rowptr);
    cudaGetSymbolAddress((void**)&cur,    g_cur);
    cudaGetSymbolAddress((void**)&eadj,   g_eadj);
    cudaGetSymbolAddress((void**)&bsum,   g_bsum);
    cudaGetSymbolAddress((void**)&boff,   g_boff);
    cudaGetSymbolAddress((void**)&dinv,   g_dinv);
    cudaGetSymbolAddress((void**)&y,      g_y);
    cudaGetSymbolAddress((void**)&hA,     g_hA);
    cudaGetSymbolAddress((void**)&hB,     g_hB);
    cudaGetSymbolAddress((void**)&psum,   g_psum);
    cudaGetSymbolAddress((void**)&pcnt,   g_pcnt);

    const int T  = 256;
    const int nb = (N + SCAN_BLK - 1) / SCAN_BLK;

    // CSR build + normalization
    k_zero_cnt <<<(N + T - 1) / T, T>>>(cnt, N);
    k_count    <<<(E + T - 1) / T, T>>>(ei, cnt, E);
    k_dinv     <<<(N + T - 1) / T, T>>>(cnt, dinv, N);
    k_blocksum <<<nb, 256>>>(cnt, bsum, N);
    k_scanbsum <<<1, 128>>>(bsum, boff, rowptr, nb, N, E);
    k_scanblock<<<nb, SCAN_BLK>>>(cnt, boff, rowptr, cur, N);
    k_fill     <<<(E + T - 1) / T, T>>>(ei, cur, eadj, E);
    k_zero_pool<<<(G * (DD/4) + T - 1) / T, T>>>(psum, pcnt, G);

    // 4 GCN layers
    const float4* hin = (const float4*)x;
    const int gemmBlocks = (N + BM - 1) / BM;
    const int nodeWarpBlocks = (N + 7) / 8;
    for (int L = 0; L < 4; L++) {
        const float4* W4 = (const float4*)(Ws + (size_t)L * DD * DD);
        k_gemm_tf32<<<gemmBlocks, 256>>>(hin, W4, y, dinv, N, L > 0 ? 1 : 0);
        float4* hout = (L & 1) ? hB : hA;
        if (L < 3) {
            k_scatter_csr<<<nodeWarpBlocks, 256>>>((const uint2*)y, rowptr, eadj, dinv,
                                                   bs + L * DD, hout,
                                                   nullptr, nullptr, nullptr, N);
            hin = hout;
        } else {
            k_scatter_csr<<<nodeWarpBlocks, 256>>>((const uint2*)y, rowptr, eadj, dinv,
                                                   bs + L * DD, nullptr,
                                                   batch, psum, pcnt, N);
        }
    }

    k_mlp<<<G, 128>>>(psum, pcnt, w1, b1, w2, b2, out, H);
}